// round 4
// baseline (speedup 1.0000x reference)
#include <cuda_runtime.h>
#include <math.h>

#define BATCH 8
#define NPTS  1024
#define KNN   20
#define EPSV  1e-5f
#define SLOPE 0.2f

// ---------------- scratch (static device globals; no allocation) ----------------
__device__ float g_x0t[BATCH*NPTS*3];     // transposed input (B,N,3)
__device__ float g_x1 [BATCH*NPTS*64];    // (B,N,64)
__device__ float g_x2 [BATCH*NPTS*64];
__device__ float g_x3 [BATCH*NPTS*128];
__device__ float g_x4 [BATCH*NPTS*256];
__device__ float g_xx [BATCH*NPTS];
__device__ float g_D  [(size_t)BATCH*NPTS*NPTS];   // 33.5MB: dist matrix, reused for E
__device__ int   g_idx[BATCH*NPTS*KNN];
__device__ float g_At [BATCH*NPTS*256];   // A = x @ w1^T   (B,N,O)
__device__ float g_Bt [BATCH*NPTS*256];   // Bd = x @ (w2-w1)^T
__device__ float g_pool[BATCH*2048];
__device__ float g_h1 [BATCH*512];
__device__ float g_h2 [BATCH*256];

// ---------------- kernels ----------------

__global__ void transpose_x0_kernel(const float* __restrict__ x) {
    int i = blockIdx.x*blockDim.x + threadIdx.x;   // b*N+n
    if (i >= BATCH*NPTS) return;
    int b = i / NPTS, n = i % NPTS;
#pragma unroll
    for (int c = 0; c < 3; c++)
        g_x0t[(size_t)i*3 + c] = x[((size_t)b*3 + c)*NPTS + n];
}

__global__ void xx_kernel(const float* __restrict__ xt, int C) {
    int i = blockIdx.x*blockDim.x + threadIdx.x;
    if (i >= BATCH*NPTS) return;
    const float* p = xt + (size_t)i*C;
    float s = 0.f;
    for (int c = 0; c < C; c++) s += p[c]*p[c];
    g_xx[i] = s;
}

// D[b][n][m] = xx[n] + xx[m] - 2 * sum_c x[n][c]*x[m][c]
__global__ __launch_bounds__(256)
void dist_kernel(const float* __restrict__ xt, int C) {
    __shared__ float As[16][65];
    __shared__ float Bs[16][65];
    int b  = blockIdx.z;
    int n0 = blockIdx.y*64, m0 = blockIdx.x*64;
    const float* X = xt + (size_t)b*NPTS*C;
    int tid = threadIdx.x;
    int ty = tid >> 4, tx = tid & 15;
    float acc[4][4] = {};
    for (int k0 = 0; k0 < C; k0 += 16) {
#pragma unroll
        for (int t = 0; t < 4; t++) {
            int e = tid + 256*t;
            int i = e >> 4, kk = e & 15;
            int c = k0 + kk;
            As[kk][i] = (c < C) ? X[(size_t)(n0+i)*C + c] : 0.f;
            Bs[kk][i] = (c < C) ? X[(size_t)(m0+i)*C + c] : 0.f;
        }
        __syncthreads();
#pragma unroll
        for (int kk = 0; kk < 16; kk++) {
            float a[4], bb[4];
#pragma unroll
            for (int i = 0; i < 4; i++) a[i]  = As[kk][ty*4+i];
#pragma unroll
            for (int j = 0; j < 4; j++) bb[j] = Bs[kk][tx*4+j];
#pragma unroll
            for (int i = 0; i < 4; i++)
#pragma unroll
                for (int j = 0; j < 4; j++) acc[i][j] = fmaf(a[i], bb[j], acc[i][j]);
        }
        __syncthreads();
    }
    float* Dp = g_D + (size_t)b*NPTS*NPTS;
#pragma unroll
    for (int i = 0; i < 4; i++) {
        int n = n0 + ty*4 + i;
        float xn = g_xx[b*NPTS + n];
#pragma unroll
        for (int j = 0; j < 4; j++) {
            int m = m0 + tx*4 + j;
            Dp[(size_t)n*NPTS + m] = xn + g_xx[b*NPTS + m] - 2.f*acc[i][j];
        }
    }
}

// one warp per (b,n) row: 20 iterations of global argmin with masking
__global__ __launch_bounds__(256)
void topk_kernel() {
    int warp = (blockIdx.x*blockDim.x + threadIdx.x) >> 5;
    int lane = threadIdx.x & 31;
    if (warp >= BATCH*NPTS) return;
    const float* row = g_D + (size_t)warp*NPTS;
    float d[32];
#pragma unroll
    for (int t = 0; t < 32; t++) d[t] = row[t*32 + lane];
    int* out = g_idx + warp*KNN;
    for (int it = 0; it < KNN; it++) {
        float bv = d[0]; int bt = 0;
#pragma unroll
        for (int t = 1; t < 32; t++) if (d[t] < bv) { bv = d[t]; bt = t; }
        int bm = bt*32 + lane;
#pragma unroll
        for (int off = 16; off; off >>= 1) {
            float ov = __shfl_down_sync(0xffffffffu, bv, off);
            int   om = __shfl_down_sync(0xffffffffu, bm, off);
            if (ov < bv || (ov == bv && om < bm)) { bv = ov; bm = om; }
        }
        bm = __shfl_sync(0xffffffffu, bm, 0);
        if (lane == 0) out[it] = bm;
        if ((bm & 31) == lane) {
            int tt = bm >> 5;
#pragma unroll
            for (int t = 0; t < 32; t++) if (t == tt) d[t] = 3.4e38f;
        }
    }
}

// A[b][n][o] = sum_c x[b][n][c]*w1[o][c];  Bd with (w2-w1). w is (O, 2C) row-major.
__global__ __launch_bounds__(256)
void wgemm_kernel(const float* __restrict__ xt, const float* __restrict__ w,
                  int C, int O) {
    __shared__ float Xs [16][65];
    __shared__ float W1s[16][65];
    __shared__ float Wds[16][65];
    int b  = blockIdx.z;
    int n0 = blockIdx.y*64, o0 = blockIdx.x*64;
    const float* X = xt + (size_t)b*NPTS*C;
    int tid = threadIdx.x, ty = tid >> 4, tx = tid & 15;
    float accA[4][4] = {}, accB[4][4] = {};
    for (int k0 = 0; k0 < C; k0 += 16) {
#pragma unroll
        for (int t = 0; t < 4; t++) {
            int e = tid + 256*t;
            int i = e >> 4, kk = e & 15;
            int c = k0 + kk;
            Xs[kk][i] = (c < C) ? X[(size_t)(n0+i)*C + c] : 0.f;
            if (c < C) {
                float w1 = w[(size_t)(o0+i)*2*C + c];
                float w2 = w[(size_t)(o0+i)*2*C + C + c];
                W1s[kk][i] = w1; Wds[kk][i] = w2 - w1;
            } else { W1s[kk][i] = 0.f; Wds[kk][i] = 0.f; }
        }
        __syncthreads();
#pragma unroll
        for (int kk = 0; kk < 16; kk++) {
            float a[4], w1[4], wd[4];
#pragma unroll
            for (int i = 0; i < 4; i++) a[i]  = Xs[kk][ty*4+i];
#pragma unroll
            for (int j = 0; j < 4; j++) { w1[j] = W1s[kk][tx*4+j]; wd[j] = Wds[kk][tx*4+j]; }
#pragma unroll
            for (int i = 0; i < 4; i++)
#pragma unroll
                for (int j = 0; j < 4; j++) {
                    accA[i][j] = fmaf(a[i], w1[j], accA[i][j]);
                    accB[i][j] = fmaf(a[i], wd[j], accB[i][j]);
                }
        }
        __syncthreads();
    }
#pragma unroll
    for (int i = 0; i < 4; i++) {
        int n = n0 + ty*4 + i;
#pragma unroll
        for (int j = 0; j < 4; j++) {
            int o = o0 + tx*4 + j;
            size_t off = ((size_t)b*NPTS + n)*O + o;
            g_At[off] = accA[i][j];
            g_Bt[off] = accB[i][j];
        }
    }
}

// out[b][n][o] = lrelu(bn( Bd[b][n][o] + max_k A[b][idx[n][k]][o] ))
__global__ void gathermax_kernel(const float* __restrict__ bnp, int O,
                                 float* __restrict__ out) {
    int bn_i = blockIdx.x;              // b*N+n
    int b = bn_i / NPTS;
    __shared__ int sidx[KNN];
    int o = threadIdx.x;
    if (o < KNN) sidx[o] = g_idx[bn_i*KNN + o];
    __syncthreads();
    const float* Ab = g_At + (size_t)b*NPTS*O;
    float mx = -3.4e38f;
#pragma unroll
    for (int k = 0; k < KNN; k++)
        mx = fmaxf(mx, Ab[(size_t)sidx[k]*O + o]);
    float val = g_Bt[(size_t)bn_i*O + o] + mx;
    float gam = bnp[o], bet = bnp[O+o], mu = bnp[2*O+o], var = bnp[3*O+o];
    float y = (val - mu) * (gam / sqrtf(var + EPSV)) + bet;
    out[(size_t)bn_i*O + o] = y > 0.f ? y : SLOPE*y;
}

// E[b][n][o] = lrelu(bn( sum_c cat[b][n][c] * we[o][c] )), cat = [x1|x2|x3|x4], K=512
__global__ __launch_bounds__(256)
void egemm_kernel(const float* __restrict__ we, const float* __restrict__ bne) {
    __shared__ float As[16][65];
    __shared__ float Bs[16][65];
    int b  = blockIdx.z;
    int n0 = blockIdx.y*64, o0 = blockIdx.x*64;
    int tid = threadIdx.x, ty = tid >> 4, tx = tid & 15;
    float acc[4][4] = {};
    for (int k0 = 0; k0 < 512; k0 += 16) {
        const float* src; int Cw; int cbase;
        if      (k0 < 64 ) { src = g_x1 + (size_t)b*NPTS*64;  Cw = 64;  cbase = k0;       }
        else if (k0 < 128) { src = g_x2 + (size_t)b*NPTS*64;  Cw = 64;  cbase = k0 - 64;  }
        else if (k0 < 256) { src = g_x3 + (size_t)b*NPTS*128; Cw = 128; cbase = k0 - 128; }
        else               { src = g_x4 + (size_t)b*NPTS*256; Cw = 256; cbase = k0 - 256; }
#pragma unroll
        for (int t = 0; t < 4; t++) {
            int e = tid + 256*t;
            int i = e >> 4, kk = e & 15;
            As[kk][i] = src[(size_t)(n0+i)*Cw + cbase + kk];
            Bs[kk][i] = we[(size_t)(o0+i)*512 + k0 + kk];
        }
        __syncthreads();
#pragma unroll
        for (int kk = 0; kk < 16; kk++) {
            float a[4], bb[4];
#pragma unroll
            for (int i = 0; i < 4; i++) a[i]  = As[kk][ty*4+i];
#pragma unroll
            for (int j = 0; j < 4; j++) bb[j] = Bs[kk][tx*4+j];
#pragma unroll
            for (int i = 0; i < 4; i++)
#pragma unroll
                for (int j = 0; j < 4; j++) acc[i][j] = fmaf(a[i], bb[j], acc[i][j]);
        }
        __syncthreads();
    }
    float* E = g_D + (size_t)b*NPTS*1024;
#pragma unroll
    for (int i = 0; i < 4; i++) {
        int n = n0 + ty*4 + i;
#pragma unroll
        for (int j = 0; j < 4; j++) {
            int o = o0 + tx*4 + j;
            float gam = bne[o], bet = bne[1024+o], mu = bne[2048+o], var = bne[3072+o];
            float y = (acc[i][j] - mu) * (gam / sqrtf(var + EPSV)) + bet;
            E[(size_t)n*1024 + o] = y > 0.f ? y : SLOPE*y;
        }
    }
}

__global__ void pool_kernel() {
    int b = blockIdx.y;
    int o = blockIdx.x*256 + threadIdx.x;   // 0..1023
    const float* E = g_D + (size_t)b*NPTS*1024;
    float mx = -3.4e38f, sm = 0.f;
    for (int n = 0; n < NPTS; n++) {
        float v = E[(size_t)n*1024 + o];
        mx = fmaxf(mx, v);
        sm += v;
    }
    g_pool[b*2048 + o]        = mx;
    g_pool[b*2048 + 1024 + o] = sm * (1.f/NPTS);
}

__global__ void fc_kernel(const float* __restrict__ in, const float* __restrict__ w,
                          const float* __restrict__ bnp, float* __restrict__ out,
                          int IN, int OUT) {
    int b = blockIdx.y;
    int o = blockIdx.x*blockDim.x + threadIdx.x;
    if (o >= OUT) return;
    const float* row = in + (size_t)b*IN;
    const float* wr  = w  + (size_t)o*IN;
    float s = 0.f;
    for (int i = 0; i < IN; i++) s = fmaf(row[i], wr[i], s);
    float gam = bnp[o], bet = bnp[OUT+o], mu = bnp[2*OUT+o], var = bnp[3*OUT+o];
    float y = (s - mu) * (gam / sqrtf(var + EPSV)) + bet;
    out[b*OUT + o] = y > 0.f ? y : SLOPE*y;
}

__global__ void fcfin_kernel(const float* __restrict__ w, const float* __restrict__ bias,
                             float* __restrict__ out) {
    int b = blockIdx.x;     // 8
    int o = threadIdx.x;    // 64
    float s = 0.f;
    for (int i = 0; i < 256; i++) s = fmaf(g_h2[b*256 + i], w[o*256 + i], s);
    out[b*64 + o] = s + bias[o];
}

// ---------------- launch ----------------
extern "C" void kernel_launch(void* const* d_in, const int* in_sizes, int n_in,
                              void* d_out, int out_size) {
    const float* x    = (const float*)d_in[0];
    const float* w0   = (const float*)d_in[1];
    const float* w1   = (const float*)d_in[2];
    const float* w2   = (const float*)d_in[3];
    const float* w3   = (const float*)d_in[4];
    const float* bn0  = (const float*)d_in[5];
    const float* bn1  = (const float*)d_in[6];
    const float* bn2  = (const float*)d_in[7];
    const float* bn3  = (const float*)d_in[8];
    const float* we   = (const float*)d_in[9];
    const float* bne  = (const float*)d_in[10];
    const float* wf0  = (const float*)d_in[11];
    const float* bnf0 = (const float*)d_in[12];
    const float* wf1  = (const float*)d_in[13];
    const float* bnf1 = (const float*)d_in[14];
    const float* wfin = (const float*)d_in[15];
    const float* bfin = (const float*)d_in[16];
    float* out = (float*)d_out;

    float *px0t, *px1, *px2, *px3, *px4, *ppool, *ph1, *ph2;
    cudaGetSymbolAddress((void**)&px0t, g_x0t);
    cudaGetSymbolAddress((void**)&px1,  g_x1);
    cudaGetSymbolAddress((void**)&px2,  g_x2);
    cudaGetSymbolAddress((void**)&px3,  g_x3);
    cudaGetSymbolAddress((void**)&px4,  g_x4);
    cudaGetSymbolAddress((void**)&ppool,g_pool);
    cudaGetSymbolAddress((void**)&ph1,  g_h1);
    cudaGetSymbolAddress((void**)&ph2,  g_h2);

    transpose_x0_kernel<<<(BATCH*NPTS + 255)/256, 256>>>(x);

    struct Stage { const float* xin; int C; const float* w; const float* bn; float* xout; int O; };
    Stage st[4] = {
        { px0t, 3,   w0, bn0, px1, 64  },
        { px1,  64,  w1, bn1, px2, 64  },
        { px2,  64,  w2, bn2, px3, 128 },
        { px3,  128, w3, bn3, px4, 256 },
    };

    for (int s = 0; s < 4; s++) {
        int C = st[s].C, O = st[s].O;
        xx_kernel<<<(BATCH*NPTS + 255)/256, 256>>>(st[s].xin, C);
        dist_kernel<<<dim3(NPTS/64, NPTS/64, BATCH), 256>>>(st[s].xin, C);
        topk_kernel<<<(BATCH*NPTS*32)/256, 256>>>();
        wgemm_kernel<<<dim3(O/64, NPTS/64, BATCH), 256>>>(st[s].xin, st[s].w, C, O);
        gathermax_kernel<<<BATCH*NPTS, O>>>(st[s].bn, O, st[s].xout);
    }

    egemm_kernel<<<dim3(1024/64, NPTS/64, BATCH), 256>>>(we, bne);
    pool_kernel<<<dim3(1024/256, BATCH), 256>>>();
    fc_kernel<<<dim3((512 + 255)/256, BATCH), 256>>>(ppool, wf0, bnf0, ph1, 2048, 512);
    fc_kernel<<<dim3(1, BATCH), 256>>>(ph1, wf1, bnf1, ph2, 512, 256);
    fcfin_kernel<<<BATCH, 64>>>(wfin, bfin, out);
}

// round 9
// speedup vs baseline: 1.4342x; 1.4342x over previous
#include <cuda_runtime.h>
#include <math.h>

#define BATCH 8
#define NPTS  1024
#define KNN   20
#define EPSV  1e-5f
#define SLOPE 0.2f

// ---------------- scratch (static device globals; no allocation) ----------------
__device__ float g_x0t[BATCH*NPTS*3];     // transposed input (B,N,3)
__device__ float g_x1 [BATCH*NPTS*64];    // (B,N,64)
__device__ float g_x2 [BATCH*NPTS*64];
__device__ float g_x3 [BATCH*NPTS*128];
__device__ float g_x4 [BATCH*NPTS*256];
__device__ float g_xx [BATCH*NPTS];
__device__ float g_D  [(size_t)BATCH*NPTS*NPTS];   // 33.5MB: dist matrix, reused for E
__device__ int   g_idx[BATCH*NPTS*KNN];
__device__ float g_At [BATCH*NPTS*256];   // A = x @ w1^T   (B,N,O)
__device__ float g_Bt [BATCH*NPTS*256];   // Bd = x @ (w2-w1)^T
__device__ float g_pool[BATCH*2048];
__device__ float g_h1 [BATCH*512];
__device__ float g_h2 [BATCH*256];

// ---------------- small kernels ----------------

__global__ void transpose_x0_kernel(const float* __restrict__ x) {
    int i = blockIdx.x*blockDim.x + threadIdx.x;   // b*N+n
    if (i >= BATCH*NPTS) return;
    int b = i / NPTS, n = i % NPTS;
#pragma unroll
    for (int c = 0; c < 3; c++)
        g_x0t[(size_t)i*3 + c] = x[((size_t)b*3 + c)*NPTS + n];
}

__global__ void xx_kernel(const float* __restrict__ xt, int C) {
    int i = blockIdx.x*blockDim.x + threadIdx.x;
    if (i >= BATCH*NPTS) return;
    const float* p = xt + (size_t)i*C;
    float s = 0.f;
    for (int c = 0; c < C; c++) s += p[c]*p[c];
    g_xx[i] = s;
}

// ---------------- dist: D[b][n][m] = xx[n]+xx[m]-2*<x_n,x_m>  (128x128 tile) ----------------
__global__ __launch_bounds__(256)
void dist_kernel(const float* __restrict__ xt, int C) {
    __shared__ float As[8][132];
    __shared__ float Bs[8][132];
    int b  = blockIdx.z;
    int n0 = blockIdx.y*128, m0 = blockIdx.x*128;
    const float* X = xt + (size_t)b*NPTS*C;
    int tid = threadIdx.x;
    int tx = tid & 15, ty = tid >> 4;
    int lrow = tid >> 1, lhalf = tid & 1;
    float acc[2][2][4][4] = {};
    for (int k0 = 0; k0 < C; k0 += 8) {
        if ((C & 7) == 0) {
            float4 va = *(const float4*)&X[(size_t)(n0+lrow)*C + k0 + lhalf*4];
            float4 vb = *(const float4*)&X[(size_t)(m0+lrow)*C + k0 + lhalf*4];
            As[lhalf*4+0][lrow]=va.x; As[lhalf*4+1][lrow]=va.y;
            As[lhalf*4+2][lrow]=va.z; As[lhalf*4+3][lrow]=va.w;
            Bs[lhalf*4+0][lrow]=vb.x; Bs[lhalf*4+1][lrow]=vb.y;
            Bs[lhalf*4+2][lrow]=vb.z; Bs[lhalf*4+3][lrow]=vb.w;
        } else {
#pragma unroll
            for (int j = 0; j < 4; j++) {
                int c = k0 + lhalf*4 + j;
                As[lhalf*4+j][lrow] = (c < C) ? X[(size_t)(n0+lrow)*C + c] : 0.f;
                Bs[lhalf*4+j][lrow] = (c < C) ? X[(size_t)(m0+lrow)*C + c] : 0.f;
            }
        }
        __syncthreads();
#pragma unroll
        for (int kk = 0; kk < 8; kk++) {
            float4 a0 = *(const float4*)&As[kk][ty*4];
            float4 a1 = *(const float4*)&As[kk][64 + ty*4];
            float4 b0 = *(const float4*)&Bs[kk][tx*4];
            float4 b1 = *(const float4*)&Bs[kk][64 + tx*4];
            float ar[2][4] = {{a0.x,a0.y,a0.z,a0.w},{a1.x,a1.y,a1.z,a1.w}};
            float br[2][4] = {{b0.x,b0.y,b0.z,b0.w},{b1.x,b1.y,b1.z,b1.w}};
#pragma unroll
            for (int ra = 0; ra < 2; ra++)
#pragma unroll
            for (int cb = 0; cb < 2; cb++)
#pragma unroll
            for (int i = 0; i < 4; i++)
#pragma unroll
            for (int j = 0; j < 4; j++)
                acc[ra][cb][i][j] = fmaf(ar[ra][i], br[cb][j], acc[ra][cb][i][j]);
        }
        __syncthreads();
    }
    float* Dp = g_D + (size_t)b*NPTS*NPTS;
    float xm[2][4];
#pragma unroll
    for (int cb = 0; cb < 2; cb++)
#pragma unroll
    for (int j = 0; j < 4; j++)
        xm[cb][j] = g_xx[b*NPTS + m0 + cb*64 + tx*4 + j];
#pragma unroll
    for (int ra = 0; ra < 2; ra++)
#pragma unroll
    for (int i = 0; i < 4; i++) {
        int n = n0 + ra*64 + ty*4 + i;
        float xn = g_xx[b*NPTS + n];
#pragma unroll
        for (int cb = 0; cb < 2; cb++) {
            float4 v;
            v.x = xn + xm[cb][0] - 2.f*acc[ra][cb][i][0];
            v.y = xn + xm[cb][1] - 2.f*acc[ra][cb][i][1];
            v.z = xn + xm[cb][2] - 2.f*acc[ra][cb][i][2];
            v.w = xn + xm[cb][3] - 2.f*acc[ra][cb][i][3];
            *(float4*)&Dp[(size_t)n*NPTS + m0 + cb*64 + tx*4] = v;
        }
    }
}

// ---------------- topk (unchanged, proven) ----------------
__global__ __launch_bounds__(256)
void topk_kernel() {
    int warp = (blockIdx.x*blockDim.x + threadIdx.x) >> 5;
    int lane = threadIdx.x & 31;
    if (warp >= BATCH*NPTS) return;
    const float* row = g_D + (size_t)warp*NPTS;
    float d[32];
#pragma unroll
    for (int t = 0; t < 32; t++) d[t] = row[t*32 + lane];
    int* out = g_idx + warp*KNN;
    for (int it = 0; it < KNN; it++) {
        float bv = d[0]; int bt = 0;
#pragma unroll
        for (int t = 1; t < 32; t++) if (d[t] < bv) { bv = d[t]; bt = t; }
        int bm = bt*32 + lane;
#pragma unroll
        for (int off = 16; off; off >>= 1) {
            float ov = __shfl_down_sync(0xffffffffu, bv, off);
            int   om = __shfl_down_sync(0xffffffffu, bm, off);
            if (ov < bv || (ov == bv && om < bm)) { bv = ov; bm = om; }
        }
        bm = __shfl_sync(0xffffffffu, bm, 0);
        if (lane == 0) out[it] = bm;
        if ((bm & 31) == lane) {
            int tt = bm >> 5;
#pragma unroll
            for (int t = 0; t < 32; t++) if (t == tt) d[t] = 3.4e38f;
        }
    }
}

// ---------------- wgemm: A = x@w1^T, Bd = x@(w2-w1)^T  (128n x 64o, dual) ----------------
__global__ __launch_bounds__(256)
void wgemm_kernel(const float* __restrict__ xt, const float* __restrict__ w,
                  int C, int O) {
    __shared__ float Xs [8][132];
    __shared__ float W1s[8][68];
    __shared__ float Wds[8][68];
    int b  = blockIdx.z;
    int n0 = blockIdx.y*128, o0 = blockIdx.x*64;
    const float* X = xt + (size_t)b*NPTS*C;
    int tid = threadIdx.x;
    int tx = tid & 15, ty = tid >> 4;
    int lrow = tid >> 1, lhalf = tid & 1;
    float accA[2][4][4] = {}, accB[2][4][4] = {};
    for (int k0 = 0; k0 < C; k0 += 8) {
        if ((C & 7) == 0) {
            float4 va = *(const float4*)&X[(size_t)(n0+lrow)*C + k0 + lhalf*4];
            Xs[lhalf*4+0][lrow]=va.x; Xs[lhalf*4+1][lrow]=va.y;
            Xs[lhalf*4+2][lrow]=va.z; Xs[lhalf*4+3][lrow]=va.w;
            if (tid < 128) {
                int wrow = tid >> 1, whalf = tid & 1;
                const float* wr = w + (size_t)(o0+wrow)*2*C + k0 + whalf*4;
                float4 w1 = *(const float4*)wr;
                float4 w2 = *(const float4*)(wr + C);
                W1s[whalf*4+0][wrow]=w1.x; W1s[whalf*4+1][wrow]=w1.y;
                W1s[whalf*4+2][wrow]=w1.z; W1s[whalf*4+3][wrow]=w1.w;
                Wds[whalf*4+0][wrow]=w2.x-w1.x; Wds[whalf*4+1][wrow]=w2.y-w1.y;
                Wds[whalf*4+2][wrow]=w2.z-w1.z; Wds[whalf*4+3][wrow]=w2.w-w1.w;
            }
        } else {
#pragma unroll
            for (int j = 0; j < 4; j++) {
                int c = k0 + lhalf*4 + j;
                Xs[lhalf*4+j][lrow] = (c < C) ? X[(size_t)(n0+lrow)*C + c] : 0.f;
            }
            if (tid < 128) {
                int wrow = tid >> 1, whalf = tid & 1;
#pragma unroll
                for (int j = 0; j < 4; j++) {
                    int c = k0 + whalf*4 + j;
                    float w1 = 0.f, w2 = 0.f;
                    if (c < C) {
                        w1 = w[(size_t)(o0+wrow)*2*C + c];
                        w2 = w[(size_t)(o0+wrow)*2*C + C + c];
                    }
                    W1s[whalf*4+j][wrow] = w1;
                    Wds[whalf*4+j][wrow] = w2 - w1;
                }
            }
        }
        __syncthreads();
#pragma unroll
        for (int kk = 0; kk < 8; kk++) {
            float4 a0 = *(const float4*)&Xs[kk][ty*4];
            float4 a1 = *(const float4*)&Xs[kk][64 + ty*4];
            float4 w1v = *(const float4*)&W1s[kk][tx*4];
            float4 wdv = *(const float4*)&Wds[kk][tx*4];
            float ar[2][4] = {{a0.x,a0.y,a0.z,a0.w},{a1.x,a1.y,a1.z,a1.w}};
            float w1a[4] = {w1v.x,w1v.y,w1v.z,w1v.w};
            float wda[4] = {wdv.x,wdv.y,wdv.z,wdv.w};
#pragma unroll
            for (int ra = 0; ra < 2; ra++)
#pragma unroll
            for (int i = 0; i < 4; i++)
#pragma unroll
            for (int j = 0; j < 4; j++) {
                accA[ra][i][j] = fmaf(ar[ra][i], w1a[j], accA[ra][i][j]);
                accB[ra][i][j] = fmaf(ar[ra][i], wda[j], accB[ra][i][j]);
            }
        }
        __syncthreads();
    }
#pragma unroll
    for (int ra = 0; ra < 2; ra++)
#pragma unroll
    for (int i = 0; i < 4; i++) {
        int n = n0 + ra*64 + ty*4 + i;
        size_t off = ((size_t)b*NPTS + n)*O + o0 + tx*4;
        float4 va = {accA[ra][i][0], accA[ra][i][1], accA[ra][i][2], accA[ra][i][3]};
        float4 vb = {accB[ra][i][0], accB[ra][i][1], accB[ra][i][2], accB[ra][i][3]};
        *(float4*)&g_At[off] = va;
        *(float4*)&g_Bt[off] = vb;
    }
}

// ---------------- gathermax: out = lrelu(bn(Bd + max_k A[idx])) , float4 ----------------
__global__ __launch_bounds__(128)
void gathermax_kernel(const float* __restrict__ bnp, int O,
                      float* __restrict__ out) {
    int Ov = O >> 2;              // float4 lanes per point
    int G  = 128 / Ov;            // points per block (8 / 4 / 2)
    int tid = threadIdx.x;
    int ln = tid / Ov, ov = tid % Ov;
    int bn = blockIdx.x*G + ln;
    int b = bn >> 10;
    __shared__ int sidx[8][KNN];
    for (int t = tid; t < G*KNN; t += 128)
        sidx[t/KNN][t%KNN] = g_idx[(blockIdx.x*G + t/KNN)*KNN + t%KNN];
    __syncthreads();
    const float* Ab = g_At + (size_t)b*NPTS*O;
    float4 mx = make_float4(-3.4e38f, -3.4e38f, -3.4e38f, -3.4e38f);
#pragma unroll
    for (int k = 0; k < KNN; k++) {
        float4 v = *(const float4*)&Ab[(size_t)sidx[ln][k]*O + ov*4];
        mx.x = fmaxf(mx.x, v.x); mx.y = fmaxf(mx.y, v.y);
        mx.z = fmaxf(mx.z, v.z); mx.w = fmaxf(mx.w, v.w);
    }
    float4 bd = *(const float4*)&g_Bt[(size_t)bn*O + ov*4];
    float4 r;
    float* rp = &r.x; float* mp = &mx.x; float* bp = &bd.x;
#pragma unroll
    for (int c = 0; c < 4; c++) {
        int o = ov*4 + c;
        float gam = bnp[o], bet = bnp[O+o], mu = bnp[2*O+o], var = bnp[3*O+o];
        float y = (bp[c] + mp[c] - mu) * (gam / sqrtf(var + EPSV)) + bet;
        rp[c] = y > 0.f ? y : SLOPE*y;
    }
    *(float4*)&out[(size_t)bn*O + ov*4] = r;
}

// ---------------- egemm: E = lrelu(bn(cat @ we^T)), K=512 (128x128 tile) ----------------
__global__ __launch_bounds__(256)
void egemm_kernel(const float* __restrict__ we, const float* __restrict__ bne) {
    __shared__ float As[8][132];
    __shared__ float Bs[8][132];
    int b  = blockIdx.z;
    int n0 = blockIdx.y*128, o0 = blockIdx.x*128;
    int tid = threadIdx.x;
    int tx = tid & 15, ty = tid >> 4;
    int lrow = tid >> 1, lhalf = tid & 1;
    float acc[2][2][4][4] = {};
    for (int k0 = 0; k0 < 512; k0 += 8) {
        const float* src; int Cw, cbase;
        if      (k0 < 64 ) { src = g_x1 + (size_t)b*NPTS*64;  Cw = 64;  cbase = k0;       }
        else if (k0 < 128) { src = g_x2 + (size_t)b*NPTS*64;  Cw = 64;  cbase = k0 - 64;  }
        else if (k0 < 256) { src = g_x3 + (size_t)b*NPTS*128; Cw = 128; cbase = k0 - 128; }
        else               { src = g_x4 + (size_t)b*NPTS*256; Cw = 256; cbase = k0 - 256; }
        float4 va = *(const float4*)&src[(size_t)(n0+lrow)*Cw + cbase + lhalf*4];
        float4 vb = *(const float4*)&we[(size_t)(o0+lrow)*512 + k0 + lhalf*4];
        As[lhalf*4+0][lrow]=va.x; As[lhalf*4+1][lrow]=va.y;
        As[lhalf*4+2][lrow]=va.z; As[lhalf*4+3][lrow]=va.w;
        Bs[lhalf*4+0][lrow]=vb.x; Bs[lhalf*4+1][lrow]=vb.y;
        Bs[lhalf*4+2][lrow]=vb.z; Bs[lhalf*4+3][lrow]=vb.w;
        __syncthreads();
#pragma unroll
        for (int kk = 0; kk < 8; kk++) {
            float4 a0 = *(const float4*)&As[kk][ty*4];
            float4 a1 = *(const float4*)&As[kk][64 + ty*4];
            float4 b0 = *(const float4*)&Bs[kk][tx*4];
            float4 b1 = *(const float4*)&Bs[kk][64 + tx*4];
            float ar[2][4] = {{a0.x,a0.y,a0.z,a0.w},{a1.x,a1.y,a1.z,a1.w}};
            float br[2][4] = {{b0.x,b0.y,b0.z,b0.w},{b1.x,b1.y,b1.z,b1.w}};
#pragma unroll
            for (int ra = 0; ra < 2; ra++)
#pragma unroll
            for (int cb = 0; cb < 2; cb++)
#pragma unroll
            for (int i = 0; i < 4; i++)
#pragma unroll
            for (int j = 0; j < 4; j++)
                acc[ra][cb][i][j] = fmaf(ar[ra][i], br[cb][j], acc[ra][cb][i][j]);
        }
        __syncthreads();
    }
    float* E = g_D + (size_t)b*NPTS*1024;
    float sc[2][4], mu[2][4], bet[2][4];
#pragma unroll
    for (int cb = 0; cb < 2; cb++)
#pragma unroll
    for (int j = 0; j < 4; j++) {
        int o = o0 + cb*64 + tx*4 + j;
        sc [cb][j] = bne[o] / sqrtf(bne[3072+o] + EPSV);
        mu [cb][j] = bne[2048+o];
        bet[cb][j] = bne[1024+o];
    }
#pragma unroll
    for (int ra = 0; ra < 2; ra++)
#pragma unroll
    for (int i = 0; i < 4; i++) {
        int n = n0 + ra*64 + ty*4 + i;
#pragma unroll
        for (int cb = 0; cb < 2; cb++) {
            float4 v;
            float* vp = &v.x;
#pragma unroll
            for (int j = 0; j < 4; j++) {
                float y = (acc[ra][cb][i][j] - mu[cb][j]) * sc[cb][j] + bet[cb][j];
                vp[j] = y > 0.f ? y : SLOPE*y;
            }
            *(float4*)&E[(size_t)n*1024 + o0 + cb*64 + tx*4] = v;
        }
    }
}

// ---------------- pool (float4) ----------------
__global__ void pool_kernel() {
    int b = blockIdx.x;
    int ov = threadIdx.x;     // 0..255
    const float* E = g_D + (size_t)b*NPTS*1024;
    float4 mx = make_float4(-3.4e38f,-3.4e38f,-3.4e38f,-3.4e38f);
    float4 sm = make_float4(0.f,0.f,0.f,0.f);
    for (int n = 0; n < NPTS; n++) {
        float4 v = *(const float4*)&E[(size_t)n*1024 + ov*4];
        mx.x = fmaxf(mx.x, v.x); mx.y = fmaxf(mx.y, v.y);
        mx.z = fmaxf(mx.z, v.z); mx.w = fmaxf(mx.w, v.w);
        sm.x += v.x; sm.y += v.y; sm.z += v.z; sm.w += v.w;
    }
    *(float4*)&g_pool[b*2048 + ov*4] = mx;
    float4 mn = make_float4(sm.x*(1.f/NPTS), sm.y*(1.f/NPTS), sm.z*(1.f/NPTS), sm.w*(1.f/NPTS));
    *(float4*)&g_pool[b*2048 + 1024 + ov*4] = mn;
}

// ---------------- FC layers ----------------
__global__ void fc_kernel(const float* __restrict__ in, const float* __restrict__ w,
                          const float* __restrict__ bnp, float* __restrict__ out,
                          int IN, int OUT) {
    int b = blockIdx.y;
    int o = blockIdx.x*blockDim.x + threadIdx.x;
    if (o >= OUT) return;
    const float4* row = (const float4*)(in + (size_t)b*IN);
    const float4* wr  = (const float4*)(w  + (size_t)o*IN);
    float4 s4 = make_float4(0.f,0.f,0.f,0.f);
    int n4 = IN >> 2;
    for (int i = 0; i < n4; i++) {
        float4 a = row[i], c = wr[i];
        s4.x = fmaf(a.x, c.x, s4.x); s4.y = fmaf(a.y, c.y, s4.y);
        s4.z = fmaf(a.z, c.z, s4.z); s4.w = fmaf(a.w, c.w, s4.w);
    }
    float s = (s4.x + s4.y) + (s4.z + s4.w);
    float gam = bnp[o], bet = bnp[OUT+o], mu = bnp[2*OUT+o], var = bnp[3*OUT+o];
    float y = (s - mu) * (gam / sqrtf(var + EPSV)) + bet;
    out[b*OUT + o] = y > 0.f ? y : SLOPE*y;
}

__global__ void fcfin_kernel(const float* __restrict__ w, const float* __restrict__ bias,
                             float* __restrict__ out) {
    int b = blockIdx.x;     // 8
    int o = threadIdx.x;    // 64
    float s = 0.f;
    for (int i = 0; i < 256; i++) s = fmaf(g_h2[b*256 + i], w[o*256 + i], s);
    out[b*64 + o] = s + bias[o];
}

// ---------------- launch ----------------
extern "C" void kernel_launch(void* const* d_in, const int* in_sizes, int n_in,
                              void* d_out, int out_size) {
    const float* x    = (const float*)d_in[0];
    const float* w0   = (const float*)d_in[1];
    const float* w1   = (const float*)d_in[2];
    const float* w2   = (const float*)d_in[3];
    const float* w3   = (const float*)d_in[4];
    const float* bn0  = (const float*)d_in[5];
    const float* bn1  = (const float*)d_in[6];
    const float* bn2  = (const float*)d_in[7];
    const float* bn3  = (const float*)d_in[8];
    const float* we   = (const float*)d_in[9];
    const float* bne  = (const float*)d_in[10];
    const float* wf0  = (const float*)d_in[11];
    const float* bnf0 = (const float*)d_in[12];
    const float* wf1  = (const float*)d_in[13];
    const float* bnf1 = (const float*)d_in[14];
    const float* wfin = (const float*)d_in[15];
    const float* bfin = (const float*)d_in[16];
    float* out = (float*)d_out;

    float *px0t, *px1, *px2, *px3, *px4, *ppool, *ph1, *ph2;
    cudaGetSymbolAddress((void**)&px0t, g_x0t);
    cudaGetSymbolAddress((void**)&px1,  g_x1);
    cudaGetSymbolAddress((void**)&px2,  g_x2);
    cudaGetSymbolAddress((void**)&px3,  g_x3);
    cudaGetSymbolAddress((void**)&px4,  g_x4);
    cudaGetSymbolAddress((void**)&ppool,g_pool);
    cudaGetSymbolAddress((void**)&ph1,  g_h1);
    cudaGetSymbolAddress((void**)&ph2,  g_h2);

    transpose_x0_kernel<<<(BATCH*NPTS + 255)/256, 256>>>(x);

    struct Stage { const float* xin; int C; const float* w; const float* bn; float* xout; int O; };
    Stage st[4] = {
        { px0t, 3,   w0, bn0, px1, 64  },
        { px1,  64,  w1, bn1, px2, 64  },
        { px2,  64,  w2, bn2, px3, 128 },
        { px3,  128, w3, bn3, px4, 256 },
    };

    for (int s = 0; s < 4; s++) {
        int C = st[s].C, O = st[s].O;
        xx_kernel<<<(BATCH*NPTS + 255)/256, 256>>>(st[s].xin, C);
        dist_kernel<<<dim3(NPTS/128, NPTS/128, BATCH), 256>>>(st[s].xin, C);
        topk_kernel<<<(BATCH*NPTS*32)/256, 256>>>();
        wgemm_kernel<<<dim3(O/64, NPTS/128, BATCH), 256>>>(st[s].xin, st[s].w, C, O);
        int G = 128 / (O >> 2);
        gathermax_kernel<<<(BATCH*NPTS)/G, 128>>>(st[s].bn, O, st[s].xout);
    }

    egemm_kernel<<<dim3(1024/128, NPTS/128, BATCH), 256>>>(we, bne);
    pool_kernel<<<BATCH, 256>>>();
    fc_kernel<<<dim3((512 + 255)/256, BATCH), 256>>>(ppool, wf0, bnf0, ph1, 2048, 512);
    fc_kernel<<<dim3(1, BATCH), 256>>>(ph1, wf1, bnf1, ph2, 512, 256);
    fcfin_kernel<<<BATCH, 64>>>(wfin, bfin, out);
}